// round 2
// baseline (speedup 1.0000x reference)
#include <cuda_runtime.h>
#include <cuda_bf16.h>
#include <cstdint>

// ============================ problem constants ============================
#define N_ROWS 262144
#define CH     256
#define NSEG   16
#define BM     128          // rows per CTA
#define BK     64           // k-chunk
#define NCHUNK 4            // 256 / 64
#define BN_EPS 1e-5f

// ============================ smem layout ==================================
#define PA     144                    // bytes per A smem row (64 bf16 + 16B pad)
#define PB     144                    // bytes per B smem row
#define A_TILE (BM*PA)                // 18432
#define B_TILE (CH*PA)                // 36864
#define SMEM_TOTAL (4*A_TILE + 4*B_TILE)   // 221184 (2 bufs x hi/lo each)

__device__ __forceinline__ int aoff(int buf, int hl) { return buf*2*A_TILE + hl*A_TILE; }
__device__ __forceinline__ int boff(int buf, int hl) { return 4*A_TILE + buf*2*B_TILE + hl*B_TILE; }

// ============================ device scratch ===============================
__device__ float g_sums[NSEG*CH];
__device__ float g_h[NSEG*CH];
__device__ float g_D[NSEG*CH];
__device__ __nv_bfloat16 g_Whi[CH*CH];   // [n][k] = bf16_hi(W1_top[k][n]*A[n])
__device__ __nv_bfloat16 g_Wlo[CH*CH];   // [n][k] = bf16 residual
__device__ int g_so[NSEG+1];             // {0, o[0..15]}

// ============================ PTX helpers ==================================
__device__ __forceinline__ uint32_t smem_u32(const void* p) {
    uint32_t a;
    asm("{ .reg .u64 t; cvta.to.shared.u64 t, %1; cvt.u32.u64 %0, t; }"
        : "=r"(a) : "l"(p));
    return a;
}
__device__ __forceinline__ void ldsm4(uint32_t* r, uint32_t addr) {
    asm volatile("ldmatrix.sync.aligned.m8n8.x4.shared.b16 {%0,%1,%2,%3}, [%4];"
                 : "=r"(r[0]), "=r"(r[1]), "=r"(r[2]), "=r"(r[3]) : "r"(addr));
}
__device__ __forceinline__ void mma16816(float* d, const uint32_t* a, uint32_t b0, uint32_t b1) {
    asm volatile("mma.sync.aligned.m16n8k16.row.col.f32.bf16.bf16.f32 "
                 "{%0,%1,%2,%3},{%4,%5,%6,%7},{%8,%9},{%0,%1,%2,%3};"
                 : "+f"(d[0]), "+f"(d[1]), "+f"(d[2]), "+f"(d[3])
                 : "r"(a[0]), "r"(a[1]), "r"(a[2]), "r"(a[3]), "r"(b0), "r"(b1));
}
__device__ __forceinline__ void cp16(uint32_t dst, const void* src) {
    asm volatile("cp.async.cg.shared.global [%0], [%1], 16;" :: "r"(dst), "l"(src));
}
#define CP_COMMIT() asm volatile("cp.async.commit_group;" ::: "memory")
#define CP_WAIT0()  asm volatile("cp.async.wait_group 0;" ::: "memory")

__device__ __forceinline__ uint32_t pack2(__nv_bfloat16 a, __nv_bfloat16 b) {
    return (uint32_t)__bfloat16_as_ushort(a) | ((uint32_t)__bfloat16_as_ushort(b) << 16);
}

// ============================ kernel 0: zero + decode offsets ==============
__global__ void prep0_kernel(const void* __restrict__ o) {
    int t = blockIdx.x * blockDim.x + threadIdx.x;
    if (t < NSEG*CH) g_sums[t] = 0.f;
    if (t == 0) {
        const int* oi = (const int*)o;
        bool is64 = (oi[1] == 0);   // int64 LE -> high word of o[0] is 0
        g_so[0] = 0;
        for (int i = 0; i < NSEG; i++)
            g_so[i+1] = is64 ? (int)((const long long*)o)[i] : oi[i];
    }
}

// ============================ kernel 1: segment sums =======================
__global__ void segsum_kernel(const float* __restrict__ x) {
    __shared__ int so[NSEG+1];
    if (threadIdx.x <= NSEG) so[threadIdx.x] = g_so[threadIdx.x];
    __syncthreads();
    int c = threadIdx.x;
    int r = blockIdx.x * BM;
    int seg = 0;
    while (r >= so[seg+1]) seg++;
    float acc = 0.f;
    #pragma unroll 4
    for (int i = 0; i < BM; i++, r++) {
        if (r >= so[seg+1]) {
            atomicAdd(&g_sums[seg*CH + c], acc);
            acc = 0.f;
            do { seg++; } while (r >= so[seg+1]);
        }
        acc += x[(size_t)r * CH + c];
    }
    atomicAdd(&g_sums[seg*CH + c], acc);
}

// ============================ kernel 2a: h = relu(mean@W2+b2) ==============
__global__ void seg_mlp_kernel(const float* __restrict__ W2, const float* __restrict__ b2) {
    int s = blockIdx.x, c = threadIdx.x;
    __shared__ float m[CH];
    float cnt = (float)(g_so[s+1] - g_so[s]);
    m[c] = g_sums[s*CH + c] / cnt;
    __syncthreads();
    float acc = b2[c];
    #pragma unroll 8
    for (int k = 0; k < CH; k++) acc = fmaf(m[k], W2[k*CH + c], acc);
    g_h[s*CH + c] = fmaxf(acc, 0.f);
}

// ============================ kernel 2b: D[s,c] fused bias =================
__global__ void bias_kernel(const float* __restrict__ W1, const float* __restrict__ b1,
                            const float* __restrict__ gamma, const float* __restrict__ beta,
                            const float* __restrict__ rm, const float* __restrict__ rv) {
    int s = blockIdx.x, c = threadIdx.x;
    __shared__ float hs[CH];
    hs[c] = g_h[s*CH + c];
    __syncthreads();
    float acc = b1[c];
    #pragma unroll 8
    for (int k = 0; k < CH; k++) acc = fmaf(hs[k], W1[(CH + k)*CH + c], acc);
    float A = gamma[c] * rsqrtf(rv[c] + BN_EPS);
    g_D[s*CH + c] = acc * A + (beta[c] - rm[c] * A);
}

// ============================ kernel 2c: pre-split W' ======================
__global__ void wprep_kernel(const float* __restrict__ W1, const float* __restrict__ gamma,
                             const float* __restrict__ rv) {
    int n = blockIdx.x, k = threadIdx.x;
    float A = gamma[n] * rsqrtf(rv[n] + BN_EPS);
    float w = W1[k*CH + n] * A;
    __nv_bfloat16 hi = __float2bfloat16_rn(w);
    float res = w - __bfloat162float(hi);
    g_Whi[n*CH + k] = hi;
    g_Wlo[n*CH + k] = __float2bfloat16_rn(res);
}

// ============================ GEMM pieces ==================================
// Issue cp.async for B tiles (hi+lo) of chunk kc into buffer buf.
__device__ __forceinline__ void issue_B(uint32_t sb, int kc, int buf, int tid) {
    #pragma unroll
    for (int i = 0; i < 8; ++i) {
        int e = tid + i*512;        // [0, 4096): 2048 hi + 2048 lo 16B transfers
        int hl = e >> 11;
        int idx = e & 2047;
        int n = idx >> 3, q = idx & 7;
        const __nv_bfloat16* src = (hl ? g_Wlo : g_Whi) + n*CH + kc*BK + q*8;
        cp16(sb + boff(buf, hl) + n*PB + q*16, src);
    }
    CP_COMMIT();
}
// Load A chunk kc (fp32) into registers.
__device__ __forceinline__ void load_A(const float* __restrict__ x, size_t row0,
                                       int kc, int tid, float4* av) {
    #pragma unroll
    for (int i = 0; i < 4; ++i) {
        int e = tid + i*512;        // [0, 2048) float4s
        int r = e >> 4, q = e & 15;
        av[i] = *(const float4*)(x + (row0 + (size_t)r)*CH + kc*BK + q*4);
    }
}
// Convert + store A registers into smem buffer buf (hi + lo).
__device__ __forceinline__ void store_A(uint32_t sb, char* smem, int buf, int tid,
                                        const float4* av) {
    #pragma unroll
    for (int i = 0; i < 4; ++i) {
        int e = tid + i*512;
        int r = e >> 4, q = e & 15;
        float4 v = av[i];
        __nv_bfloat16 h0 = __float2bfloat16_rn(v.x), h1 = __float2bfloat16_rn(v.y);
        __nv_bfloat16 h2 = __float2bfloat16_rn(v.z), h3 = __float2bfloat16_rn(v.w);
        __nv_bfloat16 l0 = __float2bfloat16_rn(v.x - __bfloat162float(h0));
        __nv_bfloat16 l1 = __float2bfloat16_rn(v.y - __bfloat162float(h1));
        __nv_bfloat16 l2 = __float2bfloat16_rn(v.z - __bfloat162float(h2));
        __nv_bfloat16 l3 = __float2bfloat16_rn(v.w - __bfloat162float(h3));
        *(uint2*)(smem + aoff(buf,0) + r*PA + q*8) = make_uint2(pack2(h0,h1), pack2(h2,h3));
        *(uint2*)(smem + aoff(buf,1) + r*PA + q*8) = make_uint2(pack2(l0,l1), pack2(l2,l3));
    }
}

// ============================ kernel 3: mma.sync GEMM + epilogue ===========
__global__ __launch_bounds__(512, 1)
void gemm_kernel(const float* __restrict__ x, float* __restrict__ out) {
    extern __shared__ char smem[];
    uint32_t sb = smem_u32(smem);
    int tid = threadIdx.x, lane = tid & 31, wid = tid >> 5;
    int wm = wid & 3;          // warp row block: 32 rows
    int wn = wid >> 2;         // warp col block: 64 cols
    size_t row0 = (size_t)blockIdx.x * BM;

    float acc[2][8][4];
    #pragma unroll
    for (int mt = 0; mt < 2; mt++)
        #pragma unroll
        for (int nt = 0; nt < 8; nt++)
            #pragma unroll
            for (int i = 0; i < 4; i++) acc[mt][nt][i] = 0.f;

    // ---- prologue: chunk 0 into buf 0 ----
    float4 av[4];
    issue_B(sb, 0, 0, tid);
    load_A(x, row0, 0, tid, av);
    store_A(sb, smem, 0, tid, av);
    CP_WAIT0();
    __syncthreads();

    // ---- main loop over K chunks ----
    for (int kc = 0; kc < NCHUNK; ++kc) {
        int cur = kc & 1, nxt = cur ^ 1;
        if (kc < NCHUNK-1) {
            issue_B(sb, kc+1, nxt, tid);
            load_A(x, row0, kc+1, tid, av);
        }
        // 3 passes: (Ahi,Bhi), (Ahi,Blo), (Alo,Bhi)
        #pragma unroll
        for (int pass = 0; pass < 3; ++pass) {
            uint32_t abase = sb + aoff(cur, pass >> 1);
            uint32_t bbase = sb + boff(cur, pass & 1);
            uint32_t arow = abase + (wm*32 + (lane & 15))*PA + (((lane >> 4) << 3))*2;
            uint32_t brow = bbase + (wn*64 + (lane & 7) + ((lane >> 4) << 3))*PB
                                  + (((lane >> 3) & 1) * 8)*2;
            #pragma unroll
            for (int ks = 0; ks < 4; ++ks) {
                uint32_t a0[4], a1[4];
                ldsm4(a0, arow + ks*32);
                ldsm4(a1, arow + ks*32 + 16*PA);
                #pragma unroll
                for (int ntp = 0; ntp < 4; ++ntp) {
                    uint32_t b[4];
                    ldsm4(b, brow + ntp*16*PB + ks*32);
                    mma16816(acc[0][ntp*2+0], a0, b[0], b[1]);
                    mma16816(acc[0][ntp*2+1], a0, b[2], b[3]);
                    mma16816(acc[1][ntp*2+0], a1, b[0], b[1]);
                    mma16816(acc[1][ntp*2+1], a1, b[2], b[3]);
                }
            }
        }
        if (kc < NCHUNK-1) store_A(sb, smem, nxt, tid, av);
        CP_WAIT0();
        __syncthreads();
    }

    // ---- epilogue: + D[seg], ReLU, store ----
    int r = lane >> 2, c2 = (lane & 3) * 2;
    #pragma unroll
    for (int mt = 0; mt < 2; mt++) {
        #pragma unroll
        for (int half = 0; half < 2; half++) {
            int m = wm*32 + mt*16 + half*8 + r;
            size_t grow = row0 + (size_t)m;
            int seg = 0;
            while ((int)grow >= g_so[seg+1]) seg++;
            const float* Drow = g_D + seg*CH;
            float* orow = out + grow*CH;
            #pragma unroll
            for (int nt = 0; nt < 8; nt++) {
                int col = wn*64 + nt*8 + c2;
                float v0 = acc[mt][nt][half*2+0] + Drow[col];
                float v1 = acc[mt][nt][half*2+1] + Drow[col+1];
                *(float2*)(orow + col) = make_float2(fmaxf(v0, 0.f), fmaxf(v1, 0.f));
            }
        }
    }
}

// ============================ launch ======================================
extern "C" void kernel_launch(void* const* d_in, const int* in_sizes, int n_in,
                              void* d_out, int out_size) {
    const float* x     = (const float*)d_in[0];
    const void*  o     = d_in[1];
    const float* W2    = (const float*)d_in[2];
    const float* b2    = (const float*)d_in[3];
    const float* W1    = (const float*)d_in[4];
    const float* b1    = (const float*)d_in[5];
    const float* gamma = (const float*)d_in[6];
    const float* beta  = (const float*)d_in[7];
    const float* rm    = (const float*)d_in[8];
    const float* rv    = (const float*)d_in[9];
    float* out = (float*)d_out;

    cudaFuncSetAttribute(gemm_kernel, cudaFuncAttributeMaxDynamicSharedMemorySize, SMEM_TOTAL);

    prep0_kernel<<<16, 256>>>(o);
    segsum_kernel<<<N_ROWS/BM, 256>>>(x);
    seg_mlp_kernel<<<NSEG, CH>>>(W2, b2);
    bias_kernel<<<NSEG, CH>>>(W1, b1, gamma, beta, rm, rv);
    wprep_kernel<<<CH, CH>>>(W1, gamma, rv);
    gemm_kernel<<<N_ROWS/BM, 512, SMEM_TOTAL>>>(x, out);
}

// round 3
// speedup vs baseline: 2.2037x; 2.2037x over previous
#include <cuda_runtime.h>
#include <cuda_fp16.h>
#include <cstdint>

// ============================ problem constants ============================
#define N_ROWS 262144
#define CH     256
#define NSEG   16
#define BM     128          // rows per CTA
#define BK     64           // k-chunk
#define NCHUNK 4            // 256 / 64
#define BN_EPS 1e-5f

// ============================ smem layout ==================================
#define PA     144                    // bytes per smem row (64 fp16 + 16B pad)
#define A_TILE (BM*PA)                // 18432
#define B_TILE (CH*PA)                // 36864
#define SMEM_TOTAL (2*A_TILE + 2*B_TILE)   // 110592 (double-buffered)

__device__ __forceinline__ int aoff(int buf) { return buf*A_TILE; }
__device__ __forceinline__ int boff(int buf) { return 2*A_TILE + buf*B_TILE; }

// ============================ device scratch ===============================
__device__ float g_sums[NSEG*CH];
__device__ float g_D[NSEG*CH];
__device__ __half g_Wh[CH*CH];     // [n][k] = fp16(W1_top[k][n] * A[n])
__device__ int g_so[NSEG+1];       // {0, o[0..15]}

// ============================ PTX helpers ==================================
__device__ __forceinline__ uint32_t smem_u32(const void* p) {
    uint32_t a;
    asm("{ .reg .u64 t; cvta.to.shared.u64 t, %1; cvt.u32.u64 %0, t; }"
        : "=r"(a) : "l"(p));
    return a;
}
__device__ __forceinline__ void ldsm4(uint32_t* r, uint32_t addr) {
    asm volatile("ldmatrix.sync.aligned.m8n8.x4.shared.b16 {%0,%1,%2,%3}, [%4];"
                 : "=r"(r[0]), "=r"(r[1]), "=r"(r[2]), "=r"(r[3]) : "r"(addr));
}
__device__ __forceinline__ void mma16816(float* d, const uint32_t* a, uint32_t b0, uint32_t b1) {
    asm volatile("mma.sync.aligned.m16n8k16.row.col.f32.f16.f16.f32 "
                 "{%0,%1,%2,%3},{%4,%5,%6,%7},{%8,%9},{%0,%1,%2,%3};"
                 : "+f"(d[0]), "+f"(d[1]), "+f"(d[2]), "+f"(d[3])
                 : "r"(a[0]), "r"(a[1]), "r"(a[2]), "r"(a[3]), "r"(b0), "r"(b1));
}
__device__ __forceinline__ void cp16(uint32_t dst, const void* src) {
    asm volatile("cp.async.cg.shared.global [%0], [%1], 16;" :: "r"(dst), "l"(src));
}
#define CP_COMMIT() asm volatile("cp.async.commit_group;" ::: "memory")
#define CP_WAIT0()  asm volatile("cp.async.wait_group 0;" ::: "memory")

// ============================ kernel 0: zero + decode offsets ==============
__global__ void prep0_kernel(const void* __restrict__ o) {
    int t = blockIdx.x * blockDim.x + threadIdx.x;
    if (t < NSEG*CH) g_sums[t] = 0.f;
    if (t == 0) {
        const int* oi = (const int*)o;
        bool is64 = (oi[1] == 0);   // int64 LE -> high word of o[0] is 0
        g_so[0] = 0;
        for (int i = 0; i < NSEG; i++)
            g_so[i+1] = is64 ? (int)((const long long*)o)[i] : oi[i];
    }
}

// ============================ kernel 1: segment sums =======================
__global__ void segsum_kernel(const float* __restrict__ x) {
    __shared__ int so[NSEG+1];
    if (threadIdx.x <= NSEG) so[threadIdx.x] = g_so[threadIdx.x];
    __syncthreads();
    int c = threadIdx.x;
    int r = blockIdx.x * BM;
    int seg = 0;
    while (r >= so[seg+1]) seg++;
    float acc = 0.f;
    #pragma unroll 4
    for (int i = 0; i < BM; i++, r++) {
        if (r >= so[seg+1]) {
            atomicAdd(&g_sums[seg*CH + c], acc);
            acc = 0.f;
            do { seg++; } while (r >= so[seg+1]);
        }
        acc += __ldcs(x + (size_t)r * CH + c);
    }
    atomicAdd(&g_sums[seg*CH + c], acc);
}

// ================= kernel 2: fused h -> D  +  W fp16 prep ==================
__global__ void fused_prep_kernel(const float* __restrict__ W2, const float* __restrict__ b2,
                                  const float* __restrict__ W1, const float* __restrict__ b1,
                                  const float* __restrict__ gamma, const float* __restrict__ beta,
                                  const float* __restrict__ rm, const float* __restrict__ rv) {
    int b = blockIdx.x, c = threadIdx.x;
    if (b < NSEG) {
        // per-segment: mean -> h = relu(mean@W2+b2) -> D = BN-affine(h@W1_bot + b1)
        __shared__ float m[CH], hs[CH];
        int s = b;
        float cnt = (float)(g_so[s+1] - g_so[s]);
        m[c] = g_sums[s*CH + c] / cnt;
        __syncthreads();
        float acc = b2[c];
        #pragma unroll 16
        for (int k = 0; k < CH; k++) acc = fmaf(m[k], W2[k*CH + c], acc);
        hs[c] = fmaxf(acc, 0.f);
        __syncthreads();
        float acc2 = b1[c];
        #pragma unroll 16
        for (int k = 0; k < CH; k++) acc2 = fmaf(hs[k], W1[(CH + k)*CH + c], acc2);
        float A = gamma[c] * rsqrtf(rv[c] + BN_EPS);
        g_D[s*CH + c] = acc2 * A + (beta[c] - rm[c] * A);
    } else {
        // weight prep: g_Wh[n][k] = fp16(W1_top[k][n] * A[n]); blocks 16..143, 2 rows each
        int n2 = b - NSEG;
        #pragma unroll
        for (int sub = 0; sub < 2; ++sub) {
            int n = n2*2 + sub;
            float A = gamma[n] * rsqrtf(rv[n] + BN_EPS);
            g_Wh[n*CH + c] = __float2half_rn(W1[c*CH + n] * A);
        }
    }
}

// ============================ GEMM pieces ==================================
__device__ __forceinline__ void issue_B(uint32_t sb, int kc, int buf, int tid) {
    #pragma unroll
    for (int i = 0; i < 4; ++i) {
        int idx = tid + i*512;          // [0, 2048) 16B transfers
        int n = idx >> 3, q = idx & 7;
        cp16(sb + boff(buf) + n*PA + q*16, g_Wh + n*CH + kc*BK + q*8);
    }
    CP_COMMIT();
}
__device__ __forceinline__ void load_A(const float* __restrict__ x, size_t row0,
                                       int kc, int tid, float4* av) {
    #pragma unroll
    for (int i = 0; i < 4; ++i) {
        int e = tid + i*512;            // [0, 2048) float4s
        int r = e >> 4, q = e & 15;
        av[i] = __ldcs((const float4*)(x + (row0 + (size_t)r)*CH + kc*BK + q*4));
    }
}
__device__ __forceinline__ void store_A(char* smem, int buf, int tid, const float4* av) {
    #pragma unroll
    for (int i = 0; i < 4; ++i) {
        int e = tid + i*512;
        int r = e >> 4, q = e & 15;
        float4 v = av[i];
        __half2 p0 = __float22half2_rn(make_float2(v.x, v.y));
        __half2 p1 = __float22half2_rn(make_float2(v.z, v.w));
        *(uint2*)(smem + aoff(buf) + r*PA + q*8) =
            make_uint2(*(uint32_t*)&p0, *(uint32_t*)&p1);
    }
}

// ============================ kernel 3: mma.sync GEMM + epilogue ===========
__global__ __launch_bounds__(512, 1)
void gemm_kernel(const float* __restrict__ x, float* __restrict__ out) {
    extern __shared__ char smem[];
    __shared__ int sso[NSEG+1];
    uint32_t sb = smem_u32(smem);
    int tid = threadIdx.x, lane = tid & 31, wid = tid >> 5;
    int wm = wid & 3;          // warp row block: 32 rows
    int wn = wid >> 2;         // warp col block: 64 cols
    size_t row0 = (size_t)blockIdx.x * BM;

    if (tid <= NSEG) sso[tid] = g_so[tid];

    float acc[2][8][4];
    #pragma unroll
    for (int mt = 0; mt < 2; mt++)
        #pragma unroll
        for (int nt = 0; nt < 8; nt++)
            #pragma unroll
            for (int i = 0; i < 4; i++) acc[mt][nt][i] = 0.f;

    // ---- prologue: chunk 0 into buf 0 ----
    float4 av[4];
    issue_B(sb, 0, 0, tid);
    load_A(x, row0, 0, tid, av);
    store_A(smem, 0, tid, av);
    CP_WAIT0();
    __syncthreads();

    // ---- main loop over K chunks ----
    for (int kc = 0; kc < NCHUNK; ++kc) {
        int cur = kc & 1, nxt = cur ^ 1;
        if (kc < NCHUNK-1) {
            issue_B(sb, kc+1, nxt, tid);
            load_A(x, row0, kc+1, tid, av);
        }
        uint32_t arow = sb + aoff(cur) + (wm*32 + (lane & 15))*PA + ((lane >> 4) << 3)*2;
        uint32_t brow = sb + boff(cur) + (wn*64 + (lane & 7) + ((lane >> 4) << 3))*PA
                              + (((lane >> 3) & 1) * 8)*2;
        #pragma unroll
        for (int ks = 0; ks < 4; ++ks) {
            uint32_t a0[4], a1[4];
            ldsm4(a0, arow + ks*32);
            ldsm4(a1, arow + ks*32 + 16*PA);
            #pragma unroll
            for (int ntp = 0; ntp < 4; ++ntp) {
                uint32_t b[4];
                ldsm4(b, brow + ntp*16*PA + ks*32);
                mma16816(acc[0][ntp*2+0], a0, b[0], b[1]);
                mma16816(acc[0][ntp*2+1], a0, b[2], b[3]);
                mma16816(acc[1][ntp*2+0], a1, b[0], b[1]);
                mma16816(acc[1][ntp*2+1], a1, b[2], b[3]);
            }
        }
        if (kc < NCHUNK-1) store_A(smem, nxt, tid, av);
        CP_WAIT0();
        __syncthreads();
    }

    // ---- epilogue: + D[seg], ReLU, streaming store ----
    int r = lane >> 2, c2 = (lane & 3) * 2;
    #pragma unroll
    for (int mt = 0; mt < 2; mt++) {
        #pragma unroll
        for (int half = 0; half < 2; half++) {
            int m = wm*32 + mt*16 + half*8 + r;
            size_t grow = row0 + (size_t)m;
            int seg = 0;
            while ((int)grow >= sso[seg+1]) seg++;
            const float* Drow = g_D + seg*CH;
            float* orow = out + grow*CH;
            #pragma unroll
            for (int nt = 0; nt < 8; nt++) {
                int col = wn*64 + nt*8 + c2;
                float v0 = acc[mt][nt][half*2+0] + Drow[col];
                float v1 = acc[mt][nt][half*2+1] + Drow[col+1];
                __stcs((float2*)(orow + col), make_float2(fmaxf(v0, 0.f), fmaxf(v1, 0.f)));
            }
        }
    }
}

// ============================ launch ======================================
extern "C" void kernel_launch(void* const* d_in, const int* in_sizes, int n_in,
                              void* d_out, int out_size) {
    const float* x     = (const float*)d_in[0];
    const void*  o     = d_in[1];
    const float* W2    = (const float*)d_in[2];
    const float* b2    = (const float*)d_in[3];
    const float* W1    = (const float*)d_in[4];
    const float* b1    = (const float*)d_in[5];
    const float* gamma = (const float*)d_in[6];
    const float* beta  = (const float*)d_in[7];
    const float* rm    = (const float*)d_in[8];
    const float* rv    = (const float*)d_in[9];
    float* out = (float*)d_out;

    cudaFuncSetAttribute(gemm_kernel, cudaFuncAttributeMaxDynamicSharedMemorySize, SMEM_TOTAL);

    prep0_kernel<<<16, 256>>>(o);
    segsum_kernel<<<N_ROWS/BM, 256>>>(x);
    fused_prep_kernel<<<NSEG + CH/2, CH>>>(W2, b2, W1, b1, gamma, beta, rm, rv);
    gemm_kernel<<<N_ROWS/BM, 512, SMEM_TOTAL>>>(x, out);
}